// round 3
// baseline (speedup 1.0000x reference)
#include <cuda_runtime.h>
#include <cuda_bf16.h>

// ProbabilityAdjustedLoss: B=8388608 rows, logits [B,2] fp32, labels [B] int32.
// HBM-bound streaming reduction: 96 MiB in, 4 B out.
//
// Single kernel: grid-stride compute + block reduce, then deterministic
// cross-block combine via fixed-point (Q32.32) integer atomics and a
// last-block epilogue that writes the mean and resets state for graph replay.

#define BASE_STABLE 0.95f
#define BASE_CHANGE 0.05f
#define EPS_LOSS 1e-8f

#define NBLOCKS 2048
#define NTHREADS 256
#define FIXED_SCALE 4294967296.0  // 2^32

__device__ unsigned long long g_acc = 0ULL;
__device__ unsigned int g_ticket = 0u;

__device__ __forceinline__ float row_loss(float l0, float l1, int lab) {
    // p_selected = softmax probability of the labeled class:
    //   label==0: p0 = 1/(1 + exp(l1 - l0))
    //   label==1: p1 = 1/(1 + exp(l0 - l1))
    const bool stable = (lab == 0);
    const float x = stable ? (l1 - l0) : (l0 - l1);
    const float p = 1.0f / (1.0f + __expf(x));

    float w;
    if (stable) {
        const float adj = fmaxf(0.0f, p - BASE_STABLE) * (1.0f / (1.0f - BASE_STABLE));
        w = fmaxf(0.1f, 1.0f - 0.5f * adj);
    } else {
        const float adj = fmaxf(0.0f, p - BASE_CHANGE) * (1.0f / (1.0f - BASE_CHANGE));
        w = fmaxf(0.5f, 2.0f - adj);
    }
    return -w * __logf(p + EPS_LOSS);
}

__global__ void __launch_bounds__(NTHREADS)
loss_fused_kernel(const float4* __restrict__ logits2,  // 2 rows per float4
                  const int4* __restrict__ labels4,    // 4 labels per int4
                  float* __restrict__ out,
                  int nquads, float inv_B) {
    float acc = 0.0f;
    const int stride = gridDim.x * blockDim.x;
    for (int i = blockIdx.x * blockDim.x + threadIdx.x; i < nquads; i += stride) {
        const float4 lgA = logits2[2 * i + 0];
        const float4 lgB = logits2[2 * i + 1];
        const int4   lb  = labels4[i];
        acc += row_loss(lgA.x, lgA.y, lb.x);
        acc += row_loss(lgA.z, lgA.w, lb.y);
        acc += row_loss(lgB.x, lgB.y, lb.z);
        acc += row_loss(lgB.z, lgB.w, lb.w);
    }

    // Block reduction
    __shared__ float sdata[NTHREADS];
    sdata[threadIdx.x] = acc;
    __syncthreads();
    #pragma unroll
    for (int s = NTHREADS / 2; s > 32; s >>= 1) {
        if (threadIdx.x < s) sdata[threadIdx.x] += sdata[threadIdx.x + s];
        __syncthreads();
    }

    __shared__ bool s_is_last;
    if (threadIdx.x < 32) {
        float v = sdata[threadIdx.x] + sdata[threadIdx.x + 32];
        #pragma unroll
        for (int off = 16; off > 0; off >>= 1)
            v += __shfl_down_sync(0xFFFFFFFFu, v, off);

        if (threadIdx.x == 0) {
            // Deterministic cross-block combine: Q32.32 fixed-point integer add
            // (integer addition is associative -> same result on every replay).
            long long q = llrint((double)v * FIXED_SCALE);
            atomicAdd(&g_acc, (unsigned long long)q);
            __threadfence();
            unsigned int t = atomicAdd(&g_ticket, 1u);
            s_is_last = (t == (unsigned int)(gridDim.x - 1));
        }
    }
    __syncthreads();

    // Last block writes the mean and resets state for the next graph replay.
    if (s_is_last && threadIdx.x == 0) {
        unsigned long long total = atomicAdd(&g_acc, 0ULL);  // coherent read
        out[0] = (float)(((double)(long long)total / FIXED_SCALE) * (double)inv_B);
        g_acc = 0ULL;
        g_ticket = 0u;
    }
}

extern "C" void kernel_launch(void* const* d_in, const int* in_sizes, int n_in,
                              void* d_out, int out_size) {
    const float4* logits2 = (const float4*)d_in[0];  // [B,2] fp32 -> B/2 float4
    const int4*   labels4 = (const int4*)d_in[1];    // [B] int32 -> B/4 int4
    const int B = in_sizes[1];                       // label element count
    const int nquads = B / 4;                        // B divisible by 4

    loss_fused_kernel<<<NBLOCKS, NTHREADS>>>(logits2, labels4, (float*)d_out,
                                             nquads, 1.0f / (float)B);
}

// round 4
// speedup vs baseline: 1.0135x; 1.0135x over previous
#include <cuda_runtime.h>
#include <cuda_bf16.h>

// ProbabilityAdjustedLoss: B=8388608 rows, logits [B,2] fp32, labels [B] int32.
// HBM-bound streaming reduction: 96 MiB in, 4 B out.
//
// Math: for selected class, -log(p_sel) = log(1 + exp(x)) with x the
// sign-selected logit difference. No division on the log path; p_sel only
// feeds the (stop-gradient) weight, via one fast MUFU rcp.
// Weight is branchless: w = max(floor, fma(-slope, max(0, p-thresh), base))
// with the 4 constants selected by label.
//
// Single kernel, 8 rows/thread-iteration (front-batched 4x float4 + 2x int4).
// Deterministic cross-block combine: Q32.32 fixed-point integer atomics,
// last block writes mean and resets state for graph replay.

#define NBLOCKS 2048
#define NTHREADS 256
#define FIXED_SCALE 4294967296.0  // 2^32

__device__ unsigned long long g_acc = 0ULL;
__device__ unsigned int g_ticket = 0u;

__device__ __forceinline__ float row_loss(float l0, float l1, int lab) {
    const bool stable = (lab == 0);
    const float d = l1 - l0;
    const float x = stable ? d : -d;         // x s.t. p_sel = 1/(1+exp(x))
    const float u = 1.0f + __expf(x);        // 1/p_sel
    const float p = __fdividef(1.0f, u);     // MUFU rcp (approx), weight only

    // weight constants by label
    const float thresh = stable ? 0.95f : 0.05f;
    const float slope  = stable ? 10.0f : (1.0f / 0.95f);
    const float basev  = stable ? 1.0f  : 2.0f;
    const float floorv = stable ? 0.1f  : 0.5f;
    const float w = fmaxf(floorv, fmaf(-slope, fmaxf(0.0f, p - thresh), basev));

    return w * __logf(u);                    // = -w * log(p_sel)
}

__global__ void __launch_bounds__(NTHREADS)
loss_fused_kernel(const float4* __restrict__ logits2,  // 2 rows per float4
                  const int4* __restrict__ labels4,    // 4 labels per int4
                  float* __restrict__ out,
                  int nocts, float inv_B) {            // groups of 8 rows
    float acc0 = 0.0f, acc1 = 0.0f;
    const int stride = gridDim.x * blockDim.x;
    for (int i = blockIdx.x * blockDim.x + threadIdx.x; i < nocts; i += stride) {
        // Front-batched wide loads: 6x LDG.128
        const float4 lgA = logits2[4 * i + 0];
        const float4 lgB = logits2[4 * i + 1];
        const float4 lgC = logits2[4 * i + 2];
        const float4 lgD = logits2[4 * i + 3];
        const int4   lbA = labels4[2 * i + 0];
        const int4   lbB = labels4[2 * i + 1];

        acc0 += row_loss(lgA.x, lgA.y, lbA.x);
        acc1 += row_loss(lgA.z, lgA.w, lbA.y);
        acc0 += row_loss(lgB.x, lgB.y, lbA.z);
        acc1 += row_loss(lgB.z, lgB.w, lbA.w);
        acc0 += row_loss(lgC.x, lgC.y, lbB.x);
        acc1 += row_loss(lgC.z, lgC.w, lbB.y);
        acc0 += row_loss(lgD.x, lgD.y, lbB.z);
        acc1 += row_loss(lgD.z, lgD.w, lbB.w);
    }
    float acc = acc0 + acc1;

    // Block reduction
    __shared__ float sdata[NTHREADS];
    sdata[threadIdx.x] = acc;
    __syncthreads();
    #pragma unroll
    for (int s = NTHREADS / 2; s > 32; s >>= 1) {
        if (threadIdx.x < s) sdata[threadIdx.x] += sdata[threadIdx.x + s];
        __syncthreads();
    }

    __shared__ bool s_is_last;
    if (threadIdx.x < 32) {
        float v = sdata[threadIdx.x] + sdata[threadIdx.x + 32];
        #pragma unroll
        for (int off = 16; off > 0; off >>= 1)
            v += __shfl_down_sync(0xFFFFFFFFu, v, off);

        if (threadIdx.x == 0) {
            // Deterministic cross-block combine (integer add is associative).
            long long q = llrint((double)v * FIXED_SCALE);
            atomicAdd(&g_acc, (unsigned long long)q);
            __threadfence();
            unsigned int t = atomicAdd(&g_ticket, 1u);
            s_is_last = (t == (unsigned int)(gridDim.x - 1));
        }
    }
    __syncthreads();

    // Last block writes the mean and resets state for the next graph replay.
    if (s_is_last && threadIdx.x == 0) {
        unsigned long long total = atomicAdd(&g_acc, 0ULL);  // coherent read
        out[0] = (float)(((double)(long long)total / FIXED_SCALE) * (double)inv_B);
        g_acc = 0ULL;
        g_ticket = 0u;
    }
}

extern "C" void kernel_launch(void* const* d_in, const int* in_sizes, int n_in,
                              void* d_out, int out_size) {
    const float4* logits2 = (const float4*)d_in[0];  // [B,2] fp32 -> B/2 float4
    const int4*   labels4 = (const int4*)d_in[1];    // [B] int32 -> B/4 int4
    const int B = in_sizes[1];                       // label element count
    const int nocts = B / 8;                         // B divisible by 8

    loss_fused_kernel<<<NBLOCKS, NTHREADS>>>(logits2, labels4, (float*)d_out,
                                             nocts, 1.0f / (float)B);
}

// round 5
// speedup vs baseline: 1.1385x; 1.1233x over previous
#include <cuda_runtime.h>
#include <cuda_bf16.h>

// ProbabilityAdjustedLoss: B=8388608 rows, logits [B,2] fp32, labels [B] int32.
// HBM-bound streaming reduction: 96 MiB in, 4 B out.
//
// R5 = R2's load shape (4 rows/iter, 3 front-batched LDG.128 -> low L1tex
// queue pressure; R4's MLP_p1=6 raised L1% 22->40 and slowed down)
//    + R4's lean math (log path division-free, branchless weights; proved
//      bit-exact vs reference)
//    + fused deterministic epilogue (Q32.32 integer atomics, last block
//      writes mean + resets state for graph replay).

#define NBLOCKS 2048
#define NTHREADS 256
#define FIXED_SCALE 4294967296.0  // 2^32

__device__ unsigned long long g_acc = 0ULL;
__device__ unsigned int g_ticket = 0u;

__device__ __forceinline__ float row_loss(float l0, float l1, int lab) {
    const bool stable = (lab == 0);
    const float d = l1 - l0;
    const float x = stable ? d : -d;         // x s.t. p_sel = 1/(1+exp(x))
    const float u = 1.0f + __expf(x);        // 1/p_sel
    const float p = __fdividef(1.0f, u);     // MUFU rcp, weight path only

    // label-selected weight constants; branchless clamp-fma-clamp
    const float thresh = stable ? 0.95f : 0.05f;
    const float slope  = stable ? 10.0f : (1.0f / 0.95f);
    const float basev  = stable ? 1.0f  : 2.0f;
    const float floorv = stable ? 0.1f  : 0.5f;
    const float w = fmaxf(floorv, fmaf(-slope, fmaxf(0.0f, p - thresh), basev));

    return w * __logf(u);                    // = -w * log(p_sel)
}

__global__ void __launch_bounds__(NTHREADS)
loss_fused_kernel(const float4* __restrict__ logits2,  // 2 rows per float4
                  const int4* __restrict__ labels4,    // 4 labels per int4
                  float* __restrict__ out,
                  int nquads, float inv_B) {           // groups of 4 rows
    float acc = 0.0f;
    const int stride = gridDim.x * blockDim.x;
    for (int i = blockIdx.x * blockDim.x + threadIdx.x; i < nquads; i += stride) {
        // 3 front-batched wide loads (MLP_p1 = 3)
        const float4 lgA = logits2[2 * i + 0];
        const float4 lgB = logits2[2 * i + 1];
        const int4   lb  = labels4[i];
        acc += row_loss(lgA.x, lgA.y, lb.x);
        acc += row_loss(lgA.z, lgA.w, lb.y);
        acc += row_loss(lgB.x, lgB.y, lb.z);
        acc += row_loss(lgB.z, lgB.w, lb.w);
    }

    // Block reduction
    __shared__ float sdata[NTHREADS];
    sdata[threadIdx.x] = acc;
    __syncthreads();
    #pragma unroll
    for (int s = NTHREADS / 2; s > 32; s >>= 1) {
        if (threadIdx.x < s) sdata[threadIdx.x] += sdata[threadIdx.x + s];
        __syncthreads();
    }

    __shared__ bool s_is_last;
    if (threadIdx.x < 32) {
        float v = sdata[threadIdx.x] + sdata[threadIdx.x + 32];
        #pragma unroll
        for (int off = 16; off > 0; off >>= 1)
            v += __shfl_down_sync(0xFFFFFFFFu, v, off);

        if (threadIdx.x == 0) {
            // Deterministic cross-block combine (integer add is associative).
            long long q = llrint((double)v * FIXED_SCALE);
            atomicAdd(&g_acc, (unsigned long long)q);
            __threadfence();
            unsigned int t = atomicAdd(&g_ticket, 1u);
            s_is_last = (t == (unsigned int)(gridDim.x - 1));
        }
    }
    __syncthreads();

    // Last block writes the mean and resets state for the next graph replay.
    if (s_is_last && threadIdx.x == 0) {
        unsigned long long total = atomicAdd(&g_acc, 0ULL);  // coherent read
        out[0] = (float)(((double)(long long)total / FIXED_SCALE) * (double)inv_B);
        g_acc = 0ULL;
        g_ticket = 0u;
    }
}

extern "C" void kernel_launch(void* const* d_in, const int* in_sizes, int n_in,
                              void* d_out, int out_size) {
    const float4* logits2 = (const float4*)d_in[0];  // [B,2] fp32 -> B/2 float4
    const int4*   labels4 = (const int4*)d_in[1];    // [B] int32 -> B/4 int4
    const int B = in_sizes[1];                       // label element count
    const int nquads = B / 4;

    loss_fused_kernel<<<NBLOCKS, NTHREADS>>>(logits2, labels4, (float*)d_out,
                                             nquads, 1.0f / (float)B);
}

// round 6
// speedup vs baseline: 1.2903x; 1.1333x over previous
#include <cuda_runtime.h>
#include <cuda_bf16.h>

// ProbabilityAdjustedLoss: B=8388608 rows, logits [B,2] fp32, labels [B] int32.
// HBM-bound streaming reduction: 96 MiB in, 4 B out.
//
// R6 = R5 (winner: 4 rows/iter, MLP_p1=3, lean division-free math, fused
// deterministic Q32.32 integer-atomic epilogue) + single-wave launch:
// grid = 148 SMs * 8 CTAs = 1184 blocks, all resident simultaneously.
// R5's 2048-block launch ran 1.73 waves -> second wave only 73% full,
// capping DRAM at 63%. One elastic resident wave keeps HBM saturated
// end-to-end.

#define NBLOCKS 1184   // 148 SMs * 8 CTAs/SM = exactly one full wave
#define NTHREADS 256
#define FIXED_SCALE 4294967296.0  // 2^32

__device__ unsigned long long g_acc = 0ULL;
__device__ unsigned int g_ticket = 0u;

__device__ __forceinline__ float row_loss(float l0, float l1, int lab) {
    const bool stable = (lab == 0);
    const float d = l1 - l0;
    const float x = stable ? d : -d;         // x s.t. p_sel = 1/(1+exp(x))
    const float u = 1.0f + __expf(x);        // 1/p_sel
    const float p = __fdividef(1.0f, u);     // MUFU rcp, weight path only

    // label-selected weight constants; branchless clamp-fma-clamp
    const float thresh = stable ? 0.95f : 0.05f;
    const float slope  = stable ? 10.0f : (1.0f / 0.95f);
    const float basev  = stable ? 1.0f  : 2.0f;
    const float floorv = stable ? 0.1f  : 0.5f;
    const float w = fmaxf(floorv, fmaf(-slope, fmaxf(0.0f, p - thresh), basev));

    return w * __logf(u);                    // = -w * log(p_sel)
}

__global__ void __launch_bounds__(NTHREADS, 8)
loss_fused_kernel(const float4* __restrict__ logits2,  // 2 rows per float4
                  const int4* __restrict__ labels4,    // 4 labels per int4
                  float* __restrict__ out,
                  int nquads, float inv_B) {           // groups of 4 rows
    float acc = 0.0f;
    const int stride = gridDim.x * blockDim.x;
    for (int i = blockIdx.x * blockDim.x + threadIdx.x; i < nquads; i += stride) {
        // 3 front-batched wide loads (MLP_p1 = 3)
        const float4 lgA = logits2[2 * i + 0];
        const float4 lgB = logits2[2 * i + 1];
        const int4   lb  = labels4[i];
        acc += row_loss(lgA.x, lgA.y, lb.x);
        acc += row_loss(lgA.z, lgA.w, lb.y);
        acc += row_loss(lgB.x, lgB.y, lb.z);
        acc += row_loss(lgB.z, lgB.w, lb.w);
    }

    // Block reduction
    __shared__ float sdata[NTHREADS];
    sdata[threadIdx.x] = acc;
    __syncthreads();
    #pragma unroll
    for (int s = NTHREADS / 2; s > 32; s >>= 1) {
        if (threadIdx.x < s) sdata[threadIdx.x] += sdata[threadIdx.x + s];
        __syncthreads();
    }

    __shared__ bool s_is_last;
    if (threadIdx.x < 32) {
        float v = sdata[threadIdx.x] + sdata[threadIdx.x + 32];
        #pragma unroll
        for (int off = 16; off > 0; off >>= 1)
            v += __shfl_down_sync(0xFFFFFFFFu, v, off);

        if (threadIdx.x == 0) {
            // Deterministic cross-block combine (integer add is associative).
            long long q = llrint((double)v * FIXED_SCALE);
            atomicAdd(&g_acc, (unsigned long long)q);
            __threadfence();
            unsigned int t = atomicAdd(&g_ticket, 1u);
            s_is_last = (t == (unsigned int)(gridDim.x - 1));
        }
    }
    __syncthreads();

    // Last block writes the mean and resets state for the next graph replay.
    if (s_is_last && threadIdx.x == 0) {
        unsigned long long total = atomicAdd(&g_acc, 0ULL);  // coherent read
        out[0] = (float)(((double)(long long)total / FIXED_SCALE) * (double)inv_B);
        g_acc = 0ULL;
        g_ticket = 0u;
    }
}

extern "C" void kernel_launch(void* const* d_in, const int* in_sizes, int n_in,
                              void* d_out, int out_size) {
    const float4* logits2 = (const float4*)d_in[0];  // [B,2] fp32 -> B/2 float4
    const int4*   labels4 = (const int4*)d_in[1];    // [B] int32 -> B/4 int4
    const int B = in_sizes[1];                       // label element count
    const int nquads = B / 4;

    loss_fused_kernel<<<NBLOCKS, NTHREADS>>>(logits2, labels4, (float*)d_out,
                                             nquads, 1.0f / (float)B);
}